// round 1
// baseline (speedup 1.0000x reference)
#include <cuda_runtime.h>

// Problem constants
constexpr int B  = 8;
constexpr int C  = 128;
constexpr int H  = 128;
constexpr int W  = 128;
constexpr int NH = 31;          // (128-8)/4+1
constexpr int NW = 31;
constexpr int NPATCH = B * NH * NW;   // 7688
constexpr float SCALE = 0.08838834764831845f;   // 1/sqrt(128)

// smem layout (floats):
//   qsh  [128][64]  at 0       (8192)
//   ksh  [128][64]  at 8192    (8192)
//   Psh  [64][64]   at 16384   (4096)
//   vsh  [128][65]  aliases offset 0 (8320 < 16384) after QK phase
constexpr int SMEM_FLOATS = 128 * 64 * 2 + 64 * 64;   // 20480
constexpr int SMEM_BYTES  = SMEM_FLOATS * 4;          // 81920

__global__ __launch_bounds__(256, 2)
void patch_attn_kernel(const float* __restrict__ q,
                       const float* __restrict__ k,
                       const float* __restrict__ v,
                       float* __restrict__ out)
{
    extern __shared__ float sm[];
    float* qsh = sm;            // [c][t], stride 64
    float* ksh = sm + 8192;     // [c][t], stride 64
    float* Psh = sm + 16384;    // [t][s], stride 64
    float* vsh = sm;            // [c][s], stride 65 (aliases q/k region)

    const int patch = blockIdx.x;
    const int b   = patch / (NH * NW);
    const int rem = patch - b * (NH * NW);
    const int h0  = (rem / NW) * 4;
    const int w0  = (rem % NW) * 4;
    const int tid = threadIdx.x;

    const float* qb = q + (size_t)b * C * H * W;
    const float* kb = k + (size_t)b * C * H * W;
    const float* vb = v + (size_t)b * C * H * W;
    float*       ob = out + (size_t)b * C * H * W;

    // ---- Load q, k tiles: 2048 float4 each, [c][t] layout ----
    {
        float4*       q4 = reinterpret_cast<float4*>(qsh);
        float4*       k4 = reinterpret_cast<float4*>(ksh);
        for (int idx = tid; idx < 2048; idx += 256) {
            int c  = idx >> 4;
            int r  = idx & 15;       // float4 slot within 64 tokens
            int t0 = r << 2;
            int i  = t0 >> 3;
            int j  = t0 & 7;         // 0 or 4
            size_t g = ((size_t)c * H + h0 + i) * W + w0 + j;
            q4[idx] = *reinterpret_cast<const float4*>(qb + g);
            k4[idx] = *reinterpret_cast<const float4*>(kb + g);
        }
    }
    __syncthreads();

    // ---- QK^T: 4x4 register tile per thread ----
    {
        const int tx = tid & 15;    // s block: s = tx*4 .. tx*4+3
        const int ty = tid >> 4;    // t block: t = ty*4 .. ty*4+3
        float acc[4][4] = {};
        const float4* q4 = reinterpret_cast<const float4*>(qsh);
        const float4* k4 = reinterpret_cast<const float4*>(ksh);
        #pragma unroll 4
        for (int c = 0; c < 128; c++) {
            float4 qv = q4[c * 16 + ty];
            float4 kv = k4[c * 16 + tx];
            float qa[4] = {qv.x, qv.y, qv.z, qv.w};
            float ka[4] = {kv.x, kv.y, kv.z, kv.w};
            #pragma unroll
            for (int a = 0; a < 4; a++)
                #pragma unroll
                for (int bb = 0; bb < 4; bb++)
                    acc[a][bb] += qa[a] * ka[bb];
        }
        float4* P4 = reinterpret_cast<float4*>(Psh);
        #pragma unroll
        for (int a = 0; a < 4; a++) {
            float4 sv = make_float4(acc[a][0] * SCALE, acc[a][1] * SCALE,
                                    acc[a][2] * SCALE, acc[a][3] * SCALE);
            P4[(ty * 4 + a) * 16 + tx] = sv;
        }
    }
    __syncthreads();   // scores in Psh; qsh/ksh now dead

    // ---- Load v tile into aliased region, [c][s] stride 65 ----
    // (safe: vsh region no longer read; Psh untouched)
    for (int idx = tid; idx < 2048; idx += 256) {
        int c  = idx >> 4;
        int r  = idx & 15;
        int t0 = r << 2;
        int i  = t0 >> 3;
        int j  = t0 & 7;
        float4 val = *reinterpret_cast<const float4*>(
            vb + ((size_t)c * H + h0 + i) * W + w0 + j);
        float* d = vsh + c * 65 + t0;
        d[0] = val.x; d[1] = val.y; d[2] = val.z; d[3] = val.w;
    }

    // ---- Softmax over rows of Psh (reads values written before the sync) ----
    {
        const int warp = tid >> 5;
        const int lane = tid & 31;
        for (int r = warp; r < 64; r += 8) {
            float x0 = Psh[r * 64 + lane];
            float x1 = Psh[r * 64 + lane + 32];
            float m = fmaxf(x0, x1);
            #pragma unroll
            for (int o = 16; o; o >>= 1)
                m = fmaxf(m, __shfl_xor_sync(0xFFFFFFFFu, m, o));
            float e0 = __expf(x0 - m);
            float e1 = __expf(x1 - m);
            float s = e0 + e1;
            #pragma unroll
            for (int o = 16; o; o >>= 1)
                s += __shfl_xor_sync(0xFFFFFFFFu, s, o);
            float inv = 1.0f / s;
            Psh[r * 64 + lane]      = e0 * inv;
            Psh[r * 64 + lane + 32] = e1 * inv;
        }
    }
    __syncthreads();   // Psh normalized, vsh loaded

    // ---- P @ V: 4 (t) x 8 (c) register tile per thread ----
    {
        const int cx = tid & 15;     // c = cx + 16*jj
        const int py = tid >> 4;     // t = py*4 + a
        float zacc[4][8] = {};
        #pragma unroll 4
        for (int s = 0; s < 64; s++) {
            float p0 = Psh[(py * 4 + 0) * 64 + s];
            float p1 = Psh[(py * 4 + 1) * 64 + s];
            float p2 = Psh[(py * 4 + 2) * 64 + s];
            float p3 = Psh[(py * 4 + 3) * 64 + s];
            #pragma unroll
            for (int jj = 0; jj < 8; jj++) {
                float vv = vsh[(cx + 16 * jj) * 65 + s];
                zacc[0][jj] += p0 * vv;
                zacc[1][jj] += p1 * vv;
                zacc[2][jj] += p2 * vv;
                zacc[3][jj] += p3 * vv;
            }
        }
        // ---- scatter-add into output ----
        #pragma unroll
        for (int a = 0; a < 4; a++) {
            int t = py * 4 + a;
            int i = t >> 3;
            int j = t & 7;
            int off = (h0 + i) * W + w0 + j;
            #pragma unroll
            for (int jj = 0; jj < 8; jj++) {
                int c = cx + 16 * jj;
                atomicAdd(ob + (size_t)c * H * W + off, zacc[a][jj]);
            }
        }
    }
}

__global__ void zero_kernel(float4* p, int n4)
{
    int i = blockIdx.x * blockDim.x + threadIdx.x;
    if (i < n4) p[i] = make_float4(0.f, 0.f, 0.f, 0.f);
}

extern "C" void kernel_launch(void* const* d_in, const int* in_sizes, int n_in,
                              void* d_out, int out_size)
{
    const float* q = (const float*)d_in[0];
    const float* k = (const float*)d_in[1];
    const float* v = (const float*)d_in[2];
    float* out = (float*)d_out;

    cudaFuncSetAttribute(patch_attn_kernel,
                         cudaFuncAttributeMaxDynamicSharedMemorySize, SMEM_BYTES);

    int n4 = (B * C * H * W) / 4;
    zero_kernel<<<(n4 + 255) / 256, 256>>>((float4*)out, n4);
    patch_attn_kernel<<<NPATCH, 256, SMEM_BYTES>>>(q, k, v, out);
}

// round 2
// speedup vs baseline: 1.0044x; 1.0044x over previous
#include <cuda_runtime.h>

// Problem constants
constexpr int B  = 8;
constexpr int C  = 128;
constexpr int H  = 128;
constexpr int W  = 128;
constexpr int NH = 31;          // (128-8)/4+1
constexpr int NW = 31;
constexpr int NPATCH = B * NH * NW;   // 7688
constexpr float SCALE = 0.08838834764831845f;   // 1/sqrt(128)

// smem layout (floats):
//   qsh  [128][64]  at 0       (8192)
//   ksh  [128][64]  at 8192    (8192)
//   Psh  [64][64]   at 16384   (4096)
//   vsh  [128][65]  aliases offset 0 (8320 < 16384) after QK phase
constexpr int SMEM_FLOATS = 128 * 64 * 2 + 64 * 64;   // 20480
constexpr int SMEM_BYTES  = SMEM_FLOATS * 4;          // 81920

__global__ __launch_bounds__(256, 2)
void patch_attn_kernel(const float* __restrict__ q,
                       const float* __restrict__ k,
                       const float* __restrict__ v,
                       float* __restrict__ out)
{
    extern __shared__ float sm[];
    float* qsh = sm;            // [c][t], stride 64
    float* ksh = sm + 8192;     // [c][t], stride 64
    float* Psh = sm + 16384;    // [t][s], stride 64
    float* vsh = sm;            // [c][s], stride 65 (aliases q/k region)

    const int patch = blockIdx.x;
    const int b   = patch / (NH * NW);
    const int rem = patch - b * (NH * NW);
    const int h0  = (rem / NW) * 4;
    const int w0  = (rem % NW) * 4;
    const int tid = threadIdx.x;

    const float* qb = q + (size_t)b * C * H * W;
    const float* kb = k + (size_t)b * C * H * W;
    const float* vb = v + (size_t)b * C * H * W;
    float*       ob = out + (size_t)b * C * H * W;

    // ---- Load q, k tiles: 2048 float4 each, [c][t] layout ----
    {
        float4*       q4 = reinterpret_cast<float4*>(qsh);
        float4*       k4 = reinterpret_cast<float4*>(ksh);
        for (int idx = tid; idx < 2048; idx += 256) {
            int c  = idx >> 4;
            int r  = idx & 15;       // float4 slot within 64 tokens
            int t0 = r << 2;
            int i  = t0 >> 3;
            int j  = t0 & 7;         // 0 or 4
            size_t g = ((size_t)c * H + h0 + i) * W + w0 + j;
            q4[idx] = *reinterpret_cast<const float4*>(qb + g);
            k4[idx] = *reinterpret_cast<const float4*>(kb + g);
        }
    }
    __syncthreads();

    // ---- QK^T: 4x4 register tile per thread ----
    {
        const int tx = tid & 15;    // s block: s = tx*4 .. tx*4+3
        const int ty = tid >> 4;    // t block: t = ty*4 .. ty*4+3
        float acc[4][4] = {};
        const float4* q4 = reinterpret_cast<const float4*>(qsh);
        const float4* k4 = reinterpret_cast<const float4*>(ksh);
        #pragma unroll 4
        for (int c = 0; c < 128; c++) {
            float4 qv = q4[c * 16 + ty];
            float4 kv = k4[c * 16 + tx];
            float qa[4] = {qv.x, qv.y, qv.z, qv.w};
            float ka[4] = {kv.x, kv.y, kv.z, kv.w};
            #pragma unroll
            for (int a = 0; a < 4; a++)
                #pragma unroll
                for (int bb = 0; bb < 4; bb++)
                    acc[a][bb] += qa[a] * ka[bb];
        }
        float4* P4 = reinterpret_cast<float4*>(Psh);
        #pragma unroll
        for (int a = 0; a < 4; a++) {
            float4 sv = make_float4(acc[a][0] * SCALE, acc[a][1] * SCALE,
                                    acc[a][2] * SCALE, acc[a][3] * SCALE);
            P4[(ty * 4 + a) * 16 + tx] = sv;
        }
    }
    __syncthreads();   // scores in Psh; qsh/ksh now dead

    // ---- Load v tile into aliased region, [c][s] stride 65 ----
    // (safe: vsh region no longer read; Psh untouched)
    for (int idx = tid; idx < 2048; idx += 256) {
        int c  = idx >> 4;
        int r  = idx & 15;
        int t0 = r << 2;
        int i  = t0 >> 3;
        int j  = t0 & 7;
        float4 val = *reinterpret_cast<const float4*>(
            vb + ((size_t)c * H + h0 + i) * W + w0 + j);
        float* d = vsh + c * 65 + t0;
        d[0] = val.x; d[1] = val.y; d[2] = val.z; d[3] = val.w;
    }

    // ---- Softmax over rows of Psh (reads values written before the sync) ----
    {
        const int warp = tid >> 5;
        const int lane = tid & 31;
        for (int r = warp; r < 64; r += 8) {
            float x0 = Psh[r * 64 + lane];
            float x1 = Psh[r * 64 + lane + 32];
            float m = fmaxf(x0, x1);
            #pragma unroll
            for (int o = 16; o; o >>= 1)
                m = fmaxf(m, __shfl_xor_sync(0xFFFFFFFFu, m, o));
            float e0 = __expf(x0 - m);
            float e1 = __expf(x1 - m);
            float s = e0 + e1;
            #pragma unroll
            for (int o = 16; o; o >>= 1)
                s += __shfl_xor_sync(0xFFFFFFFFu, s, o);
            float inv = 1.0f / s;
            Psh[r * 64 + lane]      = e0 * inv;
            Psh[r * 64 + lane + 32] = e1 * inv;
        }
    }
    __syncthreads();   // Psh normalized, vsh loaded

    // ---- P @ V: 4 (t) x 8 (c) register tile per thread ----
    {
        const int cx = tid & 15;     // c = cx + 16*jj
        const int py = tid >> 4;     // t = py*4 + a
        float zacc[4][8] = {};
        #pragma unroll 4
        for (int s = 0; s < 64; s++) {
            float p0 = Psh[(py * 4 + 0) * 64 + s];
            float p1 = Psh[(py * 4 + 1) * 64 + s];
            float p2 = Psh[(py * 4 + 2) * 64 + s];
            float p3 = Psh[(py * 4 + 3) * 64 + s];
            #pragma unroll
            for (int jj = 0; jj < 8; jj++) {
                float vv = vsh[(cx + 16 * jj) * 65 + s];
                zacc[0][jj] += p0 * vv;
                zacc[1][jj] += p1 * vv;
                zacc[2][jj] += p2 * vv;
                zacc[3][jj] += p3 * vv;
            }
        }
        // ---- scatter-add into output ----
        #pragma unroll
        for (int a = 0; a < 4; a++) {
            int t = py * 4 + a;
            int i = t >> 3;
            int j = t & 7;
            int off = (h0 + i) * W + w0 + j;
            #pragma unroll
            for (int jj = 0; jj < 8; jj++) {
                int c = cx + 16 * jj;
                atomicAdd(ob + (size_t)c * H * W + off, zacc[a][jj]);
            }
        }
    }
}

__global__ void zero_kernel(float4* p, int n4)
{
    int i = blockIdx.x * blockDim.x + threadIdx.x;
    if (i < n4) p[i] = make_float4(0.f, 0.f, 0.f, 0.f);
}

extern "C" void kernel_launch(void* const* d_in, const int* in_sizes, int n_in,
                              void* d_out, int out_size)
{
    const float* q = (const float*)d_in[0];
    const float* k = (const float*)d_in[1];
    const float* v = (const float*)d_in[2];
    float* out = (float*)d_out;

    cudaFuncSetAttribute(patch_attn_kernel,
                         cudaFuncAttributeMaxDynamicSharedMemorySize, SMEM_BYTES);

    int n4 = (B * C * H * W) / 4;
    zero_kernel<<<(n4 + 255) / 256, 256>>>((float4*)out, n4);
    patch_attn_kernel<<<NPATCH, 256, SMEM_BYTES>>>(q, k, v, out);
}

// round 4
// speedup vs baseline: 1.5659x; 1.5591x over previous
#include <cuda_runtime.h>
#include <cuda_bf16.h>
#include <cstdint>

constexpr int CC = 128, HH = 128, WW = 128, HW = HH * WW;
constexpr int NWIN = 31, NPP = NWIN * NWIN, NPATCH = 8 * NPP;   // 7688
constexpr float SCALE = 0.08838834764831845f;                    // 128^-0.5

// smem byte offsets
constexpr int QH = 0, QL = 16384, KH = 32768, KL = 49152;        // phase 1 (64 KB)
constexpr int VH = 0, VL = 16384, TB = 32768;                    // phase 2: V aliases Q, TB aliases K
constexpr int TB_STRIDE = 68;                                    // f32 row stride (conflict-free)
constexpr int SMEM_TOTAL = TB + 128 * TB_STRIDE * 4;             // 67584

__device__ float g_zbuf[(size_t)NPATCH * 64 * 128];              // [patch][c][t]

__device__ __forceinline__ uint32_t smem_u32(const void* p) {
    uint32_t a;
    asm("{ .reg .u64 t; cvta.to.shared.u64 t, %1; cvt.u32.u64 %0, t; }" : "=r"(a) : "l"(p));
    return a;
}
__device__ __forceinline__ uint32_t sw128(uint32_t off) { return off ^ ((off >> 3) & 0x70); }

__device__ __forceinline__ void sts64(uint32_t a, uint32_t v0, uint32_t v1) {
    asm volatile("st.shared.v2.b32 [%0], {%1, %2};" :: "r"(a), "r"(v0), "r"(v1) : "memory");
}
__device__ __forceinline__ void ldsm4t(uint32_t r[4], uint32_t a) {
    asm volatile("ldmatrix.sync.aligned.m8n8.x4.trans.shared.b16 {%0,%1,%2,%3}, [%4];"
                 : "=r"(r[0]), "=r"(r[1]), "=r"(r[2]), "=r"(r[3]) : "r"(a));
}
__device__ __forceinline__ void ldsm2t(uint32_t r[2], uint32_t a) {
    asm volatile("ldmatrix.sync.aligned.m8n8.x2.trans.shared.b16 {%0,%1}, [%2];"
                 : "=r"(r[0]), "=r"(r[1]) : "r"(a));
}
__device__ __forceinline__ void ldsm2(uint32_t r[2], uint32_t a) {
    asm volatile("ldmatrix.sync.aligned.m8n8.x2.shared.b16 {%0,%1}, [%2];"
                 : "=r"(r[0]), "=r"(r[1]) : "r"(a));
}
__device__ __forceinline__ void mma16816(float c[4], const uint32_t a[4], const uint32_t b[2]) {
    asm volatile(
        "mma.sync.aligned.m16n8k16.row.col.f32.bf16.bf16.f32 "
        "{%0,%1,%2,%3}, {%4,%5,%6,%7}, {%8,%9}, {%0,%1,%2,%3};"
        : "+f"(c[0]), "+f"(c[1]), "+f"(c[2]), "+f"(c[3])
        : "r"(a[0]), "r"(a[1]), "r"(a[2]), "r"(a[3]), "r"(b[0]), "r"(b[1]));
}
// split (x,y) -> hi bf16x2, lo bf16x2 with x ~= hi+lo
__device__ __forceinline__ void split2(float x, float y, uint32_t& hi, uint32_t& lo) {
    __nv_bfloat162 h = __floats2bfloat162_rn(x, y);
    float2 hf = __bfloat1622float2(h);
    __nv_bfloat162 l = __floats2bfloat162_rn(x - hf.x, y - hf.y);
    hi = *reinterpret_cast<uint32_t*>(&h);
    lo = *reinterpret_cast<uint32_t*>(&l);
}

__global__ __launch_bounds__(128, 3)
void attn_kernel(const float* __restrict__ q, const float* __restrict__ k,
                 const float* __restrict__ v)
{
    extern __shared__ char smem[];
    const uint32_t sb = smem_u32(smem);
    const int tid = threadIdx.x, wp = tid >> 5, lane = tid & 31;
    const int g = blockIdx.x;
    const int b = g / NPP, rr = g - b * NPP;
    const int h0 = (rr / NWIN) * 4, w0 = (rr % NWIN) * 4;
    const size_t pbase = (size_t)b * CC * HW + (size_t)h0 * WW + w0;

    // ---- load Q (pre-scaled), K into [c][t] bf16 hi/lo SW128 tiles ----
#pragma unroll
    for (int it = 0; it < 16; ++it) {
        int idx = tid + (it << 7);
        int c = idx >> 4, t0 = (idx & 15) << 2;
        size_t gp = pbase + (size_t)c * HW + (size_t)(t0 >> 3) * WW + (t0 & 7);
        float4 qv = *(const float4*)(q + gp);
        float4 kv = *(const float4*)(k + gp);
        uint32_t qh0, ql0, qh1, ql1, kh0, kl0, kh1, kl1;
        split2(qv.x * SCALE, qv.y * SCALE, qh0, ql0);
        split2(qv.z * SCALE, qv.w * SCALE, qh1, ql1);
        split2(kv.x, kv.y, kh0, kl0);
        split2(kv.z, kv.w, kh1, kl1);
        uint32_t off = sw128((uint32_t)(c * 128 + t0 * 2));
        sts64(sb + QH + off, qh0, qh1);
        sts64(sb + QL + off, ql0, ql1);
        sts64(sb + KH + off, kh0, kh1);
        sts64(sb + KL + off, kl0, kl1);
    }
    __syncthreads();

    // ---- phase 1: S = Q K^T  (per warp: rows 16wp..16wp+15, all 64 cols) ----
    float s[8][4];
#pragma unroll
    for (int i = 0; i < 8; ++i)
#pragma unroll
        for (int j = 0; j < 4; ++j) s[i][j] = 0.f;

    const int r8 = lane & 7, mi4 = lane >> 3, miB = mi4 & 1;
    const int dmA = (mi4 & 1) << 3, dkA = (mi4 & 2) << 2;
    const uint32_t aBase = sb + (uint32_t)((dkA + r8) * 128)
                         + (((uint32_t)(32 * wp + 2 * dmA)) ^ ((uint32_t)r8 << 4));
    const uint32_t bRow = sb + KH + (uint32_t)((8 * miB + r8) * 128);
    const uint32_t bXor = (uint32_t)r8 << 4;

    for (int kt = 0; kt < 8; ++kt) {
        uint32_t ah[4], al[4];
        uint32_t aA = aBase + kt * 2048;
        ldsm4t(ah, aA + QH);
        ldsm4t(al, aA + QL);
        uint32_t bK = bRow + kt * 2048;
#pragma unroll
        for (int nt = 0; nt < 8; ++nt) {
            uint32_t bh[2], bl[2];
            uint32_t addr = bK + (((uint32_t)(nt << 4)) ^ bXor);
            ldsm2t(bh, addr);
            ldsm2t(bl, addr + (KL - KH));
            mma16816(s[nt], ah, bh);
            mma16816(s[nt], ah, bl);
            mma16816(s[nt], al, bh);
        }
    }
    __syncthreads();   // all warps done with Q/K smem

    // ---- load V into [c][s] hi/lo tiles (aliases Q region) ----
#pragma unroll
    for (int it = 0; it < 16; ++it) {
        int idx = tid + (it << 7);
        int c = idx >> 4, t0 = (idx & 15) << 2;
        size_t gp = pbase + (size_t)c * HW + (size_t)(t0 >> 3) * WW + (t0 & 7);
        float4 vv = *(const float4*)(v + gp);
        uint32_t vh0, vl0, vh1, vl1;
        split2(vv.x, vv.y, vh0, vl0);
        split2(vv.z, vv.w, vh1, vl1);
        uint32_t off = sw128((uint32_t)(c * 128 + t0 * 2));
        sts64(sb + VH + off, vh0, vh1);
        sts64(sb + VL + off, vl0, vl1);
    }

    // ---- softmax in registers (rows live in 4 lanes: bfly 1,2) ----
    float mx0 = -1e30f, mx1 = -1e30f;
#pragma unroll
    for (int nt = 0; nt < 8; ++nt) {
        mx0 = fmaxf(mx0, fmaxf(s[nt][0], s[nt][1]));
        mx1 = fmaxf(mx1, fmaxf(s[nt][2], s[nt][3]));
    }
    mx0 = fmaxf(mx0, __shfl_xor_sync(0xFFFFFFFFu, mx0, 1));
    mx0 = fmaxf(mx0, __shfl_xor_sync(0xFFFFFFFFu, mx0, 2));
    mx1 = fmaxf(mx1, __shfl_xor_sync(0xFFFFFFFFu, mx1, 1));
    mx1 = fmaxf(mx1, __shfl_xor_sync(0xFFFFFFFFu, mx1, 2));
    float sm0 = 0.f, sm1 = 0.f;
#pragma unroll
    for (int nt = 0; nt < 8; ++nt) {
        s[nt][0] = __expf(s[nt][0] - mx0);
        s[nt][1] = __expf(s[nt][1] - mx0);
        s[nt][2] = __expf(s[nt][2] - mx1);
        s[nt][3] = __expf(s[nt][3] - mx1);
        sm0 += s[nt][0] + s[nt][1];
        sm1 += s[nt][2] + s[nt][3];
    }
    sm0 += __shfl_xor_sync(0xFFFFFFFFu, sm0, 1);
    sm0 += __shfl_xor_sync(0xFFFFFFFFu, sm0, 2);
    sm1 += __shfl_xor_sync(0xFFFFFFFFu, sm1, 1);
    sm1 += __shfl_xor_sync(0xFFFFFFFFu, sm1, 2);
    const float inv0 = 1.f / sm0, inv1 = 1.f / sm1;
    __syncthreads();   // V tiles ready

    // ---- phase 2: Z = P V  (P fragments straight from S registers) ----
    float z[16][4];
#pragma unroll
    for (int i = 0; i < 16; ++i)
#pragma unroll
        for (int j = 0; j < 4; ++j) z[i][j] = 0.f;

#pragma unroll
    for (int kt = 0; kt < 4; ++kt) {
        uint32_t ph[4], pl[4];
        split2(s[2 * kt][0] * inv0, s[2 * kt][1] * inv0, ph[0], pl[0]);
        split2(s[2 * kt][2] * inv1, s[2 * kt][3] * inv1, ph[1], pl[1]);
        split2(s[2 * kt + 1][0] * inv0, s[2 * kt + 1][1] * inv0, ph[2], pl[2]);
        split2(s[2 * kt + 1][2] * inv1, s[2 * kt + 1][3] * inv1, ph[3], pl[3]);
        uint32_t vcol = ((uint32_t)((kt << 5) + (miB << 4))) ^ ((uint32_t)r8 << 4);
#pragma unroll
        for (int nt = 0; nt < 16; ++nt) {
            uint32_t addr = sb + (uint32_t)((nt * 8 + r8) * 128) + vcol;   // VH = 0
            uint32_t bh[2], bl[2];
            ldsm2(bh, addr);
            ldsm2(bl, addr + (VL - VH));
            mma16816(z[nt], ph, bh);
            mma16816(z[nt], ph, bl);
            mma16816(z[nt], pl, bh);
        }
    }

    // ---- transpose Z to [c][t] in smem (TB region, conflict-free stride 68) ----
    float* tb = reinterpret_cast<float*>(smem + TB);
    const int trow = 16 * wp + (lane >> 2);
#pragma unroll
    for (int nt = 0; nt < 16; ++nt) {
        int c0 = 8 * nt + 2 * (lane & 3);
        tb[c0 * TB_STRIDE + trow]           = z[nt][0];
        tb[(c0 + 1) * TB_STRIDE + trow]     = z[nt][1];
        tb[c0 * TB_STRIDE + trow + 8]       = z[nt][2];
        tb[(c0 + 1) * TB_STRIDE + trow + 8] = z[nt][3];
    }
    __syncthreads();

    // ---- coalesced store to staging buffer [patch][c][t] ----
    float* zg = g_zbuf + (size_t)g * 8192;
#pragma unroll
    for (int it = 0; it < 16; ++it) {
        int idx = tid + (it << 7);
        int c = idx >> 4, f = idx & 15;
        const float* src = tb + c * TB_STRIDE + 4 * f;
        float4 val = *reinterpret_cast<const float4*>(src);
        *reinterpret_cast<float4*>(zg + c * 64 + 4 * f) = val;
    }
}

// ---- merge: out[b][c][h][w] = sum of <=4 contributors ----
__global__ __launch_bounds__(128)
void merge_kernel(float* __restrict__ out)
{
    const int h = blockIdx.x & 127;
    const int b = (blockIdx.x >> 7) & 7;
    const int cchunk = blockIdx.x >> 10;        // 0..3 -> 32 channels each
    const int w = threadIdx.x;
    const int phmin = max(0, (h - 4) >> 2), phmax = min(h >> 2, 30);
    const int pwmin = max(0, (w - 4) >> 2), pwmax = min(w >> 2, 30);
    const int pbase = b * NPP;

    for (int ci = 0; ci < 32; ++ci) {
        int c = cchunk * 32 + ci;
        float acc = 0.f;
        for (int ph = phmin; ph <= phmax; ++ph) {
            int dh = h - 4 * ph;
            const float* zp = g_zbuf
                + ((size_t)(pbase + ph * NWIN) * 128 + c) * 64 + dh * 8;
            for (int pw = pwmin; pw <= pwmax; ++pw)
                acc += zp[(size_t)pw * 8192 + (w - 4 * pw)];
        }
        out[((size_t)(b * 128 + c) * 128 + h) * 128 + w] = acc;
    }
}

extern "C" void kernel_launch(void* const* d_in, const int* in_sizes, int n_in,
                              void* d_out, int out_size)
{
    const float* q = (const float*)d_in[0];
    const float* k = (const float*)d_in[1];
    const float* v = (const float*)d_in[2];
    float* out = (float*)d_out;

    cudaFuncSetAttribute(attn_kernel,
                         cudaFuncAttributeMaxDynamicSharedMemorySize, SMEM_TOTAL);
    attn_kernel<<<NPATCH, 128, SMEM_TOTAL>>>(q, k, v);
    merge_kernel<<<8 * 128 * 4, 128>>>(out);
}

// round 5
// speedup vs baseline: 1.8403x; 1.1752x over previous
#include <cuda_runtime.h>
#include <cuda_bf16.h>
#include <cstdint>

constexpr int CC = 128, HH = 128, WW = 128, HW = HH * WW;
constexpr int NWIN = 31, NPP = NWIN * NWIN, NPATCH = 8 * NPP;   // 7688
constexpr float SCALE = 0.08838834764831845f;                    // 128^-0.5

// phase-1 chunk buffers (64 channels x 64 tokens bf16, hi/lo, Q/K) = 32 KB
constexpr int QHc = 0, QLc = 8192, KHc = 16384, KLc = 24576;
// phase-2: V tiles (128c x 64s hi/lo) alias phase-1; TB transpose buffer above
constexpr int VHo = 0, VLo = 16384, TBo = 32768;
constexpr int TB_STRIDE = 68;                                    // f32, conflict-free
constexpr int SMEM_TOTAL = TBo + 64 * TB_STRIDE * 4;             // 50176 -> 4 CTAs/SM

__device__ float g_zbuf[(size_t)NPATCH * 64 * 128];              // [patch][c][t]
__device__ float g_zpad[2048];                                   // zero dummy for merge edges

__device__ __forceinline__ uint32_t smem_u32(const void* p) {
    uint32_t a;
    asm("{ .reg .u64 t; cvta.to.shared.u64 t, %1; cvt.u32.u64 %0, t; }" : "=r"(a) : "l"(p));
    return a;
}
__device__ __forceinline__ uint32_t sw128(uint32_t off) { return off ^ ((off >> 3) & 0x70); }
__device__ __forceinline__ void sts64(uint32_t a, uint32_t v0, uint32_t v1) {
    asm volatile("st.shared.v2.b32 [%0], {%1, %2};" :: "r"(a), "r"(v0), "r"(v1) : "memory");
}
__device__ __forceinline__ void ldsm4t(uint32_t r[4], uint32_t a) {
    asm volatile("ldmatrix.sync.aligned.m8n8.x4.trans.shared.b16 {%0,%1,%2,%3}, [%4];"
                 : "=r"(r[0]), "=r"(r[1]), "=r"(r[2]), "=r"(r[3]) : "r"(a));
}
__device__ __forceinline__ void ldsm4(uint32_t r[4], uint32_t a) {
    asm volatile("ldmatrix.sync.aligned.m8n8.x4.shared.b16 {%0,%1,%2,%3}, [%4];"
                 : "=r"(r[0]), "=r"(r[1]), "=r"(r[2]), "=r"(r[3]) : "r"(a));
}
__device__ __forceinline__ void mma16816(float c[4], const uint32_t a[4], const uint32_t b[2]) {
    asm volatile(
        "mma.sync.aligned.m16n8k16.row.col.f32.bf16.bf16.f32 "
        "{%0,%1,%2,%3}, {%4,%5,%6,%7}, {%8,%9}, {%0,%1,%2,%3};"
        : "+f"(c[0]), "+f"(c[1]), "+f"(c[2]), "+f"(c[3])
        : "r"(a[0]), "r"(a[1]), "r"(a[2]), "r"(a[3]), "r"(b[0]), "r"(b[1]));
}
__device__ __forceinline__ void split2(float x, float y, uint32_t& hi, uint32_t& lo) {
    __nv_bfloat162 h = __floats2bfloat162_rn(x, y);
    float2 hf = __bfloat1622float2(h);
    __nv_bfloat162 l = __floats2bfloat162_rn(x - hf.x, y - hf.y);
    hi = *reinterpret_cast<uint32_t*>(&h);
    lo = *reinterpret_cast<uint32_t*>(&l);
}

__global__ __launch_bounds__(128, 4)
void attn_kernel(const float* __restrict__ q, const float* __restrict__ k,
                 const float* __restrict__ v)
{
    extern __shared__ char smem[];
    const uint32_t sb = smem_u32(smem);
    const int tid = threadIdx.x, wp = tid >> 5, lane = tid & 31;
    const int g = blockIdx.x;
    const int b = g / NPP, rr = g - b * NPP;
    const int h0 = (rr / NWIN) * 4, w0 = (rr % NWIN) * 4;
    const size_t pbase = (size_t)b * CC * HW + (size_t)h0 * WW + w0;

    // fragment geometry
    const int r8 = lane & 7, mi4 = lane >> 3;
    const int dmA = (mi4 & 1) << 3, dkA = (mi4 & 2) << 2;
    const uint32_t aXor = ((uint32_t)(32 * wp + 2 * dmA)) ^ ((uint32_t)r8 << 4);
    const int rowB = ((lane >> 3) & 1) * 8 + r8;   // QK B: k-row within kt block
    const int ntSel = lane >> 4;                   // second matrix pair selector
    const uint32_t rXor = (uint32_t)r8 << 4;

    float s[8][4];
#pragma unroll
    for (int i = 0; i < 8; ++i)
#pragma unroll
        for (int j = 0; j < 4; ++j) s[i][j] = 0.f;

    // ================= phase 1: S = Q K^T, two 64-channel chunks =================
    for (int ck = 0; ck < 2; ++ck) {
#pragma unroll
        for (int it = 0; it < 8; ++it) {
            int idx = tid + (it << 7);
            int cL = idx >> 4, t0 = (idx & 15) << 2;
            int c = ck * 64 + cL;
            size_t gp = pbase + (size_t)c * HW + (size_t)(t0 >> 3) * WW + (t0 & 7);
            float4 qv = *(const float4*)(q + gp);
            float4 kv = *(const float4*)(k + gp);
            uint32_t qh0, ql0, qh1, ql1, kh0, kl0, kh1, kl1;
            split2(qv.x * SCALE, qv.y * SCALE, qh0, ql0);
            split2(qv.z * SCALE, qv.w * SCALE, qh1, ql1);
            split2(kv.x, kv.y, kh0, kl0);
            split2(kv.z, kv.w, kh1, kl1);
            uint32_t off = sw128((uint32_t)(cL * 128 + t0 * 2));
            sts64(sb + QHc + off, qh0, qh1);
            sts64(sb + QLc + off, ql0, ql1);
            sts64(sb + KHc + off, kh0, kh1);
            sts64(sb + KLc + off, kl0, kl1);
        }
        __syncthreads();
#pragma unroll
        for (int kt = 0; kt < 4; ++kt) {
            uint32_t ah[4], al[4];
            uint32_t aA = sb + QHc + (uint32_t)((kt * 16 + dkA + r8) * 128) + aXor;
            ldsm4t(ah, aA);
            ldsm4t(al, aA + (QLc - QHc));
            uint32_t bRowA = sb + KHc + (uint32_t)((kt * 16 + rowB) * 128);
#pragma unroll
            for (int ntp = 0; ntp < 4; ++ntp) {
                uint32_t bh4[4], bl4[4];
                uint32_t baddr = bRowA + ((((uint32_t)(ntp * 2 + ntSel)) << 4) ^ rXor);
                ldsm4t(bh4, baddr);
                ldsm4t(bl4, baddr + (KLc - KHc));
                mma16816(s[2 * ntp], ah, bh4);
                mma16816(s[2 * ntp], ah, bl4);
                mma16816(s[2 * ntp], al, bh4);
                mma16816(s[2 * ntp + 1], ah, bh4 + 2);
                mma16816(s[2 * ntp + 1], ah, bl4 + 2);
                mma16816(s[2 * ntp + 1], al, bh4 + 2);
            }
        }
        __syncthreads();
    }

    // ---- load V [c][s] hi/lo (aliases phase-1 buffers) ----
#pragma unroll
    for (int it = 0; it < 16; ++it) {
        int idx = tid + (it << 7);
        int c = idx >> 4, t0 = (idx & 15) << 2;
        size_t gp = pbase + (size_t)c * HW + (size_t)(t0 >> 3) * WW + (t0 & 7);
        float4 vv = *(const float4*)(v + gp);
        uint32_t vh0, vl0, vh1, vl1;
        split2(vv.x, vv.y, vh0, vl0);
        split2(vv.z, vv.w, vh1, vl1);
        uint32_t off = sw128((uint32_t)(c * 128 + t0 * 2));
        sts64(sb + VHo + off, vh0, vh1);
        sts64(sb + VLo + off, vl0, vl1);
    }

    // ---- softmax in registers (row lives in 4 lanes) ----
    float mx0 = -1e30f, mx1 = -1e30f;
#pragma unroll
    for (int nt = 0; nt < 8; ++nt) {
        mx0 = fmaxf(mx0, fmaxf(s[nt][0], s[nt][1]));
        mx1 = fmaxf(mx1, fmaxf(s[nt][2], s[nt][3]));
    }
    mx0 = fmaxf(mx0, __shfl_xor_sync(~0u, mx0, 1));
    mx0 = fmaxf(mx0, __shfl_xor_sync(~0u, mx0, 2));
    mx1 = fmaxf(mx1, __shfl_xor_sync(~0u, mx1, 1));
    mx1 = fmaxf(mx1, __shfl_xor_sync(~0u, mx1, 2));
    float sm0 = 0.f, sm1 = 0.f;
#pragma unroll
    for (int nt = 0; nt < 8; ++nt) {
        s[nt][0] = __expf(s[nt][0] - mx0);
        s[nt][1] = __expf(s[nt][1] - mx0);
        s[nt][2] = __expf(s[nt][2] - mx1);
        s[nt][3] = __expf(s[nt][3] - mx1);
        sm0 += s[nt][0] + s[nt][1];
        sm1 += s[nt][2] + s[nt][3];
    }
    sm0 += __shfl_xor_sync(~0u, sm0, 1);
    sm0 += __shfl_xor_sync(~0u, sm0, 2);
    sm1 += __shfl_xor_sync(~0u, sm1, 1);
    sm1 += __shfl_xor_sync(~0u, sm1, 2);
    const float inv0 = 1.f / sm0, inv1 = 1.f / sm1;
    __syncthreads();   // V visible

    // ================= phase 2: Z = P V, two 64-channel halves =================
    float* tb = reinterpret_cast<float*>(smem + TBo);
    float* zg = g_zbuf + (size_t)g * 8192;
    const int trow = 16 * wp + (lane >> 2);

    for (int half = 0; half < 2; ++half) {
        float z[8][4];
#pragma unroll
        for (int i = 0; i < 8; ++i)
#pragma unroll
            for (int j = 0; j < 4; ++j) z[i][j] = 0.f;

#pragma unroll
        for (int kt = 0; kt < 4; ++kt) {
            uint32_t ph[4], pl[4];
            split2(s[2 * kt][0] * inv0, s[2 * kt][1] * inv0, ph[0], pl[0]);
            split2(s[2 * kt][2] * inv1, s[2 * kt][3] * inv1, ph[1], pl[1]);
            split2(s[2 * kt + 1][0] * inv0, s[2 * kt + 1][1] * inv0, ph[2], pl[2]);
            split2(s[2 * kt + 1][2] * inv1, s[2 * kt + 1][3] * inv1, ph[3], pl[3]);
            uint32_t vcol = ((uint32_t)((kt << 5) + (((lane >> 3) & 1) << 4))) ^ rXor;
#pragma unroll
            for (int ntp = 0; ntp < 4; ++ntp) {
                int row = half * 64 + ntp * 16 + ntSel * 8 + r8;
                uint32_t addr = sb + VHo + (uint32_t)(row * 128) + vcol;
                uint32_t bh4[4], bl4[4];
                ldsm4(bh4, addr);
                ldsm4(bl4, addr + (VLo - VHo));
                mma16816(z[2 * ntp], ph, bh4);
                mma16816(z[2 * ntp], ph, bl4);
                mma16816(z[2 * ntp], pl, bh4);
                mma16816(z[2 * ntp + 1], ph, bh4 + 2);
                mma16816(z[2 * ntp + 1], ph, bl4 + 2);
                mma16816(z[2 * ntp + 1], pl, bh4 + 2);
            }
        }
        // transpose z -> [c_local][t] in TB
#pragma unroll
        for (int nt = 0; nt < 8; ++nt) {
            int c0 = 8 * nt + 2 * (lane & 3);
            tb[c0 * TB_STRIDE + trow]           = z[nt][0];
            tb[(c0 + 1) * TB_STRIDE + trow]     = z[nt][1];
            tb[c0 * TB_STRIDE + trow + 8]       = z[nt][2];
            tb[(c0 + 1) * TB_STRIDE + trow + 8] = z[nt][3];
        }
        __syncthreads();
#pragma unroll
        for (int it = 0; it < 8; ++it) {
            int idx = tid + (it << 7);
            int cL = idx >> 4, f = idx & 15;
            float4 val = *reinterpret_cast<const float4*>(tb + cL * TB_STRIDE + 4 * f);
            __stcs(reinterpret_cast<float4*>(zg + (half * 64 + cL) * 64 + 4 * f), val);
        }
        __syncthreads();
    }
}

// ---- merge: out[b][c][h][w] = sum of <=4 staged contributors ----
__global__ __launch_bounds__(128)
void merge_kernel(float* __restrict__ out)
{
    const int h = blockIdx.x & 127;
    const int b = (blockIdx.x >> 7) & 7;
    const int cchunk = blockIdx.x >> 10;          // 0..3 -> 32 channels
    const int w = threadIdx.x;
    const int phmin = max(0, (h - 4) >> 2), phmax = min(h >> 2, 30);
    const int pwmin = max(0, (w - 4) >> 2), pwmax = min(w >> 2, 30);

    const float* base[4];
    int n = 0;
    for (int ph = phmin; ph <= phmax; ++ph)
        for (int pw = pwmin; pw <= pwmax; ++pw)
            base[n++] = g_zbuf
                + ((size_t)(b * NPP + ph * NWIN + pw) * 128 + cchunk * 32) * 64
                + (h - 4 * ph) * 8 + (w - 4 * pw);
    while (n < 4) base[n++] = g_zpad;

    float* op = out + ((size_t)(b * 128 + cchunk * 32) * 128 + h) * 128 + w;
#pragma unroll 4
    for (int ci = 0; ci < 32; ++ci) {
        float acc = __ldcs(base[0]) + __ldcs(base[1]) + __ldcs(base[2]) + __ldcs(base[3]);
        base[0] += 64; base[1] += 64; base[2] += 64; base[3] += 64;
        op[(size_t)ci * HW] = acc;
    }
}

extern "C" void kernel_launch(void* const* d_in, const int* in_sizes, int n_in,
                              void* d_out, int out_size)
{
    const float* q = (const float*)d_in[0];
    const float* k = (const float*)d_in[1];
    const float* v = (const float*)d_in[2];
    float* out = (float*)d_out;

    cudaFuncSetAttribute(attn_kernel,
                         cudaFuncAttributeMaxDynamicSharedMemorySize, SMEM_TOTAL);
    attn_kernel<<<NPATCH, 128, SMEM_TOTAL>>>(q, k, v);
    merge_kernel<<<8 * 128 * 4, 128>>>(out);
}